// round 6
// baseline (speedup 1.0000x reference)
#include <cuda_runtime.h>

// 32 images * 64 tiles = 2048 tiles; each tile = 4 row-slices (32 rows x 128 cols)
// 8192 slices, one per warp. Grid = 1024 CTAs x 256 thr = 8192 warps, single wave.
#define NUM_TILES  2048
#define NUM_SLICES 8192
#define NUM_CTAS   1024
__device__ float g_partials[NUM_SLICES];   // signed slice sums, [tile*4 + q]
__device__ unsigned int g_done_count = 0;

__global__ void __launch_bounds__(256, 7) lthu_kernel(
    const float* __restrict__ fake, const float* __restrict__ real,
    float* __restrict__ out)
{
    __shared__ float warp_sums[8];
    __shared__ bool is_last;

    const int lane  = threadIdx.x & 31;
    const int wid   = threadIdx.x >> 5;
    const int slice = blockIdx.x * 8 + wid;   // 0..8191

    const int tile = slice >> 2;              // 0..2047
    const int q    = slice & 3;               // row group q*32 .. q*32+31
    const int b    = tile >> 6;               // image (64 tiles per image)
    const int rem  = tile & 63;
    const int by   = rem >> 3;
    const int bx   = rem & 7;
    const long base = (long)b * (1024 * 1024)
                    + (long)(by * 128 + q * 32) * 1024
                    + (long)bx * 128;

    const float4* f4 = (const float4*)(fake + base) + lane;
    const float4* r4 = (const float4*)(real + base) + lane;
    // slice: 32 rows x 32 float4/row; row stride in float4 units = 256

    // Two independent accumulator chains; streaming (evict-first) loads:
    // data is read-once, don't let it churn L2 fill state.
    float acc0 = 0.0f, acc1 = 0.0f;
    #pragma unroll 8
    for (int r = 0; r < 32; r += 2) {
        float4 fa = __ldcs(f4 + (r    ) * 256);
        float4 ra = __ldcs(r4 + (r    ) * 256);
        float4 fb = __ldcs(f4 + (r + 1) * 256);
        float4 rb = __ldcs(r4 + (r + 1) * 256);
        acc0 += (fa.x - ra.x) + (fa.y - ra.y) + (fa.z - ra.z) + (fa.w - ra.w);
        acc1 += (fb.x - rb.x) + (fb.y - rb.y) + (fb.z - rb.z) + (fb.w - rb.w);
    }
    float acc = acc0 + acc1;

    // warp-local reduce — no CTA barrier, other warps keep streaming
    #pragma unroll
    for (int off = 16; off > 0; off >>= 1)
        acc += __shfl_xor_sync(0xFFFFFFFFu, acc, off);

    if (lane == 0)
        g_partials[slice] = acc;   // signed; abs applied per full tile later

    __syncthreads();               // single barrier, after all loads are done

    if (threadIdx.x == 0) {
        __threadfence();
        unsigned int prev = atomicAdd(&g_done_count, 1u);
        is_last = (prev == NUM_CTAS - 1);
    }
    __syncthreads();

    if (is_last) {
        // fixed-order deterministic reduce: per tile sum 4 slices, abs, sum
        float s = 0.0f;
        #pragma unroll
        for (int it = 0; it < 8; ++it) {
            int t = threadIdx.x + it * 256;        // tile 0..2047
            const float* p = &g_partials[t * 4];
            s += fabsf(p[0] + p[1] + p[2] + p[3]);
        }

        #pragma unroll
        for (int off = 16; off > 0; off >>= 1)
            s += __shfl_xor_sync(0xFFFFFFFFu, s, off);
        if (lane == 0) warp_sums[wid] = s;
        __syncthreads();
        if (wid == 0) {
            float v = (lane < 8) ? warp_sums[lane] : 0.0f;
            #pragma unroll
            for (int off = 4; off > 0; off >>= 1)
                v += __shfl_xor_sync(0xFFFFFFFFu, v, off);
            if (lane == 0) {
                out[0] = v * (1.0f / (16384.0f * 32.0f));
                g_done_count = 0;   // reset for next graph replay
            }
        }
    }
}

extern "C" void kernel_launch(void* const* d_in, const int* in_sizes, int n_in,
                              void* d_out, int out_size)
{
    const float* fake = (const float*)d_in[0];
    const float* real = (const float*)d_in[1];
    float* out = (float*)d_out;

    lthu_kernel<<<NUM_CTAS, 256>>>(fake, real, out);
}

// round 7
// speedup vs baseline: 1.0085x; 1.0085x over previous
#include <cuda_runtime.h>

// 32 images * 64 tiles = 2048 tiles; each tile = 4 row-slices (32 rows x 128 cols)
// 8192 slices, one per warp. Grid = 1024 CTAs x 256 thr = 8192 warps.
#define NUM_TILES  2048
#define NUM_SLICES 8192
#define NUM_CTAS   1024
__device__ float g_partials[NUM_SLICES];   // signed slice sums, [tile*4 + q]
__device__ unsigned int g_done_count = 0;

__global__ void __launch_bounds__(256, 4) lthu_kernel(
    const float* __restrict__ fake, const float* __restrict__ real,
    float* __restrict__ out)
{
    __shared__ float warp_sums[8];
    __shared__ bool is_last;

    const int lane  = threadIdx.x & 31;
    const int wid   = threadIdx.x >> 5;
    const int slice = blockIdx.x * 8 + wid;   // 0..8191

    const int tile = slice >> 2;              // 0..2047
    const int q    = slice & 3;               // row group q*32 .. q*32+31
    const int b    = tile >> 6;               // image (64 tiles per image)
    const int rem  = tile & 63;
    const int by   = rem >> 3;
    const int bx   = rem & 7;
    const long base = (long)b * (1024 * 1024)
                    + (long)(by * 128 + q * 32) * 1024
                    + (long)bx * 128;

    const float4* f4 = (const float4*)(fake + base) + lane;
    const float4* r4 = (const float4*)(real + base) + lane;
    // slice: 32 rows x 32 float4/row; row stride in float4 units = 256

    // Batch 8 independent LDG.128 (4 fake rows + 4 real rows) before any
    // consumption -> deep per-warp MLP. 4 independent accumulator chains.
    float a0 = 0.f, a1 = 0.f, a2 = 0.f, a3 = 0.f;
    #pragma unroll
    for (int r = 0; r < 32; r += 4) {
        float4 f0 = f4[(r + 0) * 256];
        float4 f1 = f4[(r + 1) * 256];
        float4 f2 = f4[(r + 2) * 256];
        float4 f3 = f4[(r + 3) * 256];
        float4 g0 = r4[(r + 0) * 256];
        float4 g1 = r4[(r + 1) * 256];
        float4 g2 = r4[(r + 2) * 256];
        float4 g3 = r4[(r + 3) * 256];
        a0 += (f0.x - g0.x) + (f0.y - g0.y) + (f0.z - g0.z) + (f0.w - g0.w);
        a1 += (f1.x - g1.x) + (f1.y - g1.y) + (f1.z - g1.z) + (f1.w - g1.w);
        a2 += (f2.x - g2.x) + (f2.y - g2.y) + (f2.z - g2.z) + (f2.w - g2.w);
        a3 += (f3.x - g3.x) + (f3.y - g3.y) + (f3.z - g3.z) + (f3.w - g3.w);
    }
    float acc = (a0 + a1) + (a2 + a3);

    // warp-local reduce — no CTA barrier in hot path
    #pragma unroll
    for (int off = 16; off > 0; off >>= 1)
        acc += __shfl_xor_sync(0xFFFFFFFFu, acc, off);

    if (lane == 0)
        g_partials[slice] = acc;   // signed; abs applied per full tile later

    __syncthreads();               // after all loads issued/consumed

    if (threadIdx.x == 0) {
        __threadfence();
        unsigned int prev = atomicAdd(&g_done_count, 1u);
        is_last = (prev == NUM_CTAS - 1);
    }
    __syncthreads();

    if (is_last) {
        // fixed-order deterministic reduce: per tile sum 4 slices, abs, sum
        float s = 0.0f;
        #pragma unroll
        for (int it = 0; it < 8; ++it) {
            int t = threadIdx.x + it * 256;        // tile 0..2047
            const float* p = &g_partials[t * 4];
            s += fabsf(p[0] + p[1] + p[2] + p[3]);
        }

        #pragma unroll
        for (int off = 16; off > 0; off >>= 1)
            s += __shfl_xor_sync(0xFFFFFFFFu, s, off);
        if (lane == 0) warp_sums[wid] = s;
        __syncthreads();
        if (wid == 0) {
            float v = (lane < 8) ? warp_sums[lane] : 0.0f;
            #pragma unroll
            for (int off = 4; off > 0; off >>= 1)
                v += __shfl_xor_sync(0xFFFFFFFFu, v, off);
            if (lane == 0) {
                out[0] = v * (1.0f / (16384.0f * 32.0f));
                g_done_count = 0;   // reset for next graph replay
            }
        }
    }
}

extern "C" void kernel_launch(void* const* d_in, const int* in_sizes, int n_in,
                              void* d_out, int out_size)
{
    const float* fake = (const float*)d_in[0];
    const float* real = (const float*)d_in[1];
    float* out = (float*)d_out;

    lthu_kernel<<<NUM_CTAS, 256>>>(fake, real, out);
}

// round 8
// speedup vs baseline: 1.0529x; 1.0441x over previous
#include <cuda_runtime.h>

// 32 images * 64 tiles = 2048 tiles; each tile = 4 row-slices (32 rows x 128 cols)
// 8192 slices, one per warp. 1024 CTAs x 8 warps; each CTA owns 2 whole tiles.
#define NUM_TILES  2048
#define NUM_CTAS   1024
__device__ float g_cta_sums[NUM_CTAS];   // per-CTA: |tile0 sum| + |tile1 sum|
__device__ unsigned int g_done_count = 0;

__global__ void __launch_bounds__(256, 7) lthu_kernel(
    const float* __restrict__ fake, const float* __restrict__ real,
    float* __restrict__ out)
{
    __shared__ float slice_sums[8];   // one per warp
    __shared__ float warp_sums[8];
    __shared__ bool is_last;

    const int lane  = threadIdx.x & 31;
    const int wid   = threadIdx.x >> 5;
    const int slice = blockIdx.x * 8 + wid;   // 0..8191

    const int tile = slice >> 2;              // 0..2047 (wid 0-3 -> tile 2*blk, 4-7 -> 2*blk+1)
    const int q    = slice & 3;               // row group q*32 .. q*32+31
    const int b    = tile >> 6;               // image (64 tiles per image)
    const int rem  = tile & 63;
    const int by   = rem >> 3;
    const int bx   = rem & 7;
    const long base = (long)b * (1024 * 1024)
                    + (long)(by * 128 + q * 32) * 1024
                    + (long)bx * 128;

    const float4* f4 = (const float4*)(fake + base) + lane;
    const float4* r4 = (const float4*)(real + base) + lane;
    // slice: 32 rows x 32 float4/row; row stride in float4 units = 256

    float acc = 0.0f;
    #pragma unroll 16
    for (int r = 0; r < 32; ++r) {
        float4 fv = f4[r * 256];
        float4 rv = r4[r * 256];
        acc += (fv.x - rv.x) + (fv.y - rv.y) + (fv.z - rv.z) + (fv.w - rv.w);
    }

    // warp-local reduce — no CTA barrier while other warps stream
    #pragma unroll
    for (int off = 16; off > 0; off >>= 1)
        acc += __shfl_xor_sync(0xFFFFFFFFu, acc, off);

    if (lane == 0)
        slice_sums[wid] = acc;     // signed slice sum, in shared

    __syncthreads();               // after all loads complete

    if (threadIdx.x == 0) {
        // CTA owns two complete tiles: slices 0-3 and 4-7
        float t0 = (slice_sums[0] + slice_sums[1]) + (slice_sums[2] + slice_sums[3]);
        float t1 = (slice_sums[4] + slice_sums[5]) + (slice_sums[6] + slice_sums[7]);
        g_cta_sums[blockIdx.x] = fabsf(t0) + fabsf(t1);
        __threadfence();
        unsigned int prev = atomicAdd(&g_done_count, 1u);
        is_last = (prev == NUM_CTAS - 1);
    }
    __syncthreads();

    if (is_last) {
        // fixed-order deterministic reduce of 1024 per-CTA sums
        float s = 0.0f;
        #pragma unroll
        for (int it = 0; it < 4; ++it)
            s += g_cta_sums[threadIdx.x + it * 256];

        #pragma unroll
        for (int off = 16; off > 0; off >>= 1)
            s += __shfl_xor_sync(0xFFFFFFFFu, s, off);
        if (lane == 0) warp_sums[wid] = s;
        __syncthreads();
        if (wid == 0) {
            float v = (lane < 8) ? warp_sums[lane] : 0.0f;
            #pragma unroll
            for (int off = 4; off > 0; off >>= 1)
                v += __shfl_xor_sync(0xFFFFFFFFu, v, off);
            if (lane == 0) {
                out[0] = v * (1.0f / (16384.0f * 32.0f));
                g_done_count = 0;   // reset for next graph replay
            }
        }
    }
}

extern "C" void kernel_launch(void* const* d_in, const int* in_sizes, int n_in,
                              void* d_out, int out_size)
{
    const float* fake = (const float*)d_in[0];
    const float* real = (const float*)d_in[1];
    float* out = (float*)d_out;

    lthu_kernel<<<NUM_CTAS, 256>>>(fake, real, out);
}